// round 7
// baseline (speedup 1.0000x reference)
#include <cuda_runtime.h>
#include <cuda_fp16.h>
#include <stdint.h>

// Problem constants
#define Bp    4
#define Np    50000
#define Ep    800000
#define FIN   128
#define FOUT  128
#define Mrows (Bp * Np)

#define SROW  136   // halfs per smem row (128 + 8 pad -> conflict-free ldmatrix)

// ---------------------------------------------------------------------------
// Device-global scratch (no cudaMalloc allowed)
// ---------------------------------------------------------------------------
__device__ __half g_h16[(size_t)Np * Bp * FOUT];  // 51.2 MB, layout [N][B][F]
__device__ int   g_counts[Np + 1];
__device__ int   g_offsets[Np + 1];
__device__ int   g_rank[Ep];                      // per-edge rank within its row
__device__ int   g_bsum[64];
__device__ int2  g_colval[Ep];                    // packed {col, val_bits}
__device__ int   g_idx64;

// ---------------------------------------------------------------------------
// Detect int32 vs int64 edge indices.
// ---------------------------------------------------------------------------
__global__ void detect_kernel(const int* __restrict__ er) {
    __shared__ int nz;
    if (threadIdx.x == 0) nz = 0;
    __syncthreads();
    for (int j = threadIdx.x; j < 2048; j += blockDim.x)
        if (er[2 * j + 1] != 0) nz = 1;
    __syncthreads();
    if (threadIdx.x == 0) g_idx64 = nz ? 0 : 1;
}

// ---------------------------------------------------------------------------
// Histogram of edge_row + per-edge rank (atomic return value), 4 edges/thread
// ---------------------------------------------------------------------------
__global__ void hist_kernel(const int* __restrict__ er) {
    const int idx64 = g_idx64;
    int base = (blockIdx.x * blockDim.x + threadIdx.x) * 4;
    if (base >= Ep) return;
    int r0, r1, r2, r3;
    if (base + 4 <= Ep) {
        if (idx64) {
            int4 a = __ldg((const int4*)(er + 2 * base));
            int4 b = __ldg((const int4*)(er + 2 * base + 4));
            r0 = a.x; r1 = a.z; r2 = b.x; r3 = b.z;
        } else {
            int4 a = __ldg((const int4*)(er + base));
            r0 = a.x; r1 = a.y; r2 = a.z; r3 = a.w;
        }
        int k0 = atomicAdd(&g_counts[r0], 1);
        int k1 = atomicAdd(&g_counts[r1], 1);
        int k2 = atomicAdd(&g_counts[r2], 1);
        int k3 = atomicAdd(&g_counts[r3], 1);
        *(int4*)(g_rank + base) = make_int4(k0, k1, k2, k3);
    } else {
        for (int j = base; j < Ep; j++) {
            int r = idx64 ? er[2 * j] : er[j];
            g_rank[j] = atomicAdd(&g_counts[r], 1);
        }
    }
}

// ---------------------------------------------------------------------------
// Two-level scan
// ---------------------------------------------------------------------------
__global__ __launch_bounds__(1024)
void scan1_kernel() {
    __shared__ int warpsum[32];
    const int t    = threadIdx.x;
    const int lane = t & 31;
    const int w    = t >> 5;
    int i = blockIdx.x * 1024 + t;
    int v = (i < Np) ? g_counts[i] : 0;

    int x = v;
    #pragma unroll
    for (int off = 1; off < 32; off <<= 1) {
        int y = __shfl_up_sync(0xFFFFFFFFu, x, off);
        if (lane >= off) x += y;
    }
    if (lane == 31) warpsum[w] = x;
    __syncthreads();
    if (w == 0) {
        int s = warpsum[lane];
        #pragma unroll
        for (int off = 1; off < 32; off <<= 1) {
            int y = __shfl_up_sync(0xFFFFFFFFu, s, off);
            if (lane >= off) s += y;
        }
        warpsum[lane] = s;
    }
    __syncthreads();
    int incl = x + (w > 0 ? warpsum[w - 1] : 0);
    if (i < Np) g_offsets[i] = incl;
    if (t == 1023) g_bsum[blockIdx.x] = incl;
}

__global__ void scan2_kernel(int nblocks) {
    __shared__ int sh[64];
    const int t    = threadIdx.x;
    const int lane = t & 31;
    const int w    = t >> 5;
    int v = (t < nblocks) ? g_bsum[t] : 0;
    int x = v;
    #pragma unroll
    for (int off = 1; off < 32; off <<= 1) {
        int y = __shfl_up_sync(0xFFFFFFFFu, x, off);
        if (lane >= off) x += y;
    }
    sh[t] = x;
    __syncthreads();
    int incl = x + (w == 1 ? sh[31] : 0);
    g_bsum[t] = incl - v;
    if (t == nblocks - 1) g_offsets[Np] = incl;
}

__global__ __launch_bounds__(1024)
void scan3_kernel() {
    int i = blockIdx.x * 1024 + threadIdx.x;
    if (i >= Np) return;
    g_offsets[i] = g_bsum[blockIdx.x] + g_offsets[i] - g_counts[i];
}

// ---------------------------------------------------------------------------
// Scatter edges into CSR order — no atomics (rank precomputed in hist)
// ---------------------------------------------------------------------------
__global__ void scatter_kernel(const int* __restrict__ er,
                               const int* __restrict__ ec,
                               const float* __restrict__ ev) {
    const int idx64 = g_idx64;
    int e = blockIdx.x * blockDim.x + threadIdx.x;
    if (e >= Ep) return;
    int r = idx64 ? er[2 * e] : er[e];
    int c = idx64 ? ec[2 * e] : ec[e];
    int p = g_offsets[r] + g_rank[e];
    g_colval[p] = make_int2(c, __float_as_int(ev[e]));
}

// ---------------------------------------------------------------------------
// Tensor-core GEMM: h = x @ W^T, fp16 in (converted on load), fp32 acc.
// CTA: 128x128, K=128 single pass. 8 warps, warp tile 32x64, m16n8k16.
// ---------------------------------------------------------------------------
__global__ __launch_bounds__(256, 2)
void gemm_mma_kernel(const float* __restrict__ A, const float* __restrict__ W) {
    extern __shared__ __half smem[];
    __half* sA = smem;                  // 128 x SROW
    __half* sB = smem + 128 * SROW;     // 128 x SROW

    const int tid  = threadIdx.x;
    const int lane = tid & 31;
    const int wid  = tid >> 5;
    const long blockM = (long)blockIdx.x * 128;

    {
        int row   = tid >> 1;
        int cbase = (tid & 1) * 64;
        long gr = blockM + row;
        bool valid = gr < Mrows;
        const float4* src = (const float4*)(A + gr * 128 + cbase);
        __half* dst = sA + row * SROW + cbase;
        #pragma unroll
        for (int i = 0; i < 16; i++) {
            float4 v = valid ? __ldg(src + i) : make_float4(0.f, 0.f, 0.f, 0.f);
            *(__half2*)(dst + i * 4)     = __floats2half2_rn(v.x, v.y);
            *(__half2*)(dst + i * 4 + 2) = __floats2half2_rn(v.z, v.w);
        }
        const float4* wsrc = (const float4*)(W + row * 128 + cbase);
        __half* wdst = sB + row * SROW + cbase;
        #pragma unroll
        for (int i = 0; i < 16; i++) {
            float4 v = __ldg(wsrc + i);
            *(__half2*)(wdst + i * 4)     = __floats2half2_rn(v.x, v.y);
            *(__half2*)(wdst + i * 4 + 2) = __floats2half2_rn(v.z, v.w);
        }
    }
    __syncthreads();

    const int wm = wid & 3;
    const int wn = wid >> 2;
    const int a_row = wm * 32;
    const int b_n   = wn * 64;

    float acc[2][8][4];
    #pragma unroll
    for (int i = 0; i < 2; i++)
        #pragma unroll
        for (int j = 0; j < 8; j++)
            #pragma unroll
            for (int q = 0; q < 4; q++) acc[i][j][q] = 0.f;

    uint32_t sA_base = (uint32_t)__cvta_generic_to_shared(sA);
    uint32_t sB_base = (uint32_t)__cvta_generic_to_shared(sB);

    #pragma unroll
    for (int kk = 0; kk < 8; kk++) {
        uint32_t a[2][4];
        #pragma unroll
        for (int i = 0; i < 2; i++) {
            uint32_t addr = sA_base +
                (((a_row + i * 16 + (lane & 15)) * SROW + kk * 16 + (lane >> 4) * 8) << 1);
            asm volatile(
                "ldmatrix.sync.aligned.m8n8.x4.shared.b16 {%0,%1,%2,%3}, [%4];"
                : "=r"(a[i][0]), "=r"(a[i][1]), "=r"(a[i][2]), "=r"(a[i][3])
                : "r"(addr));
        }
        uint32_t b[8][2];
        #pragma unroll
        for (int j = 0; j < 8; j++) {
            int ln   = lane & 7;
            int koff = (lane & 8) ? 8 : 0;
            uint32_t addr = sB_base +
                (((b_n + j * 8 + ln) * SROW + kk * 16 + koff) << 1);
            asm volatile(
                "ldmatrix.sync.aligned.m8n8.x2.shared.b16 {%0,%1}, [%2];"
                : "=r"(b[j][0]), "=r"(b[j][1]) : "r"(addr));
        }
        #pragma unroll
        for (int i = 0; i < 2; i++)
            #pragma unroll
            for (int j = 0; j < 8; j++)
                asm volatile(
                    "mma.sync.aligned.m16n8k16.row.col.f32.f16.f16.f32 "
                    "{%0,%1,%2,%3}, {%4,%5,%6,%7}, {%8,%9}, {%0,%1,%2,%3};"
                    : "+f"(acc[i][j][0]), "+f"(acc[i][j][1]),
                      "+f"(acc[i][j][2]), "+f"(acc[i][j][3])
                    : "r"(a[i][0]), "r"(a[i][1]), "r"(a[i][2]), "r"(a[i][3]),
                      "r"(b[j][0]), "r"(b[j][1]));
    }

    __syncthreads();
    #pragma unroll
    for (int i = 0; i < 2; i++) {
        int row0 = a_row + i * 16 + (lane >> 2);
        #pragma unroll
        for (int j = 0; j < 8; j++) {
            int col = b_n + j * 8 + (lane & 3) * 2;
            *(__half2*)(sA + row0 * SROW + col) =
                __floats2half2_rn(acc[i][j][0], acc[i][j][1]);
            *(__half2*)(sA + (row0 + 8) * SROW + col) =
                __floats2half2_rn(acc[i][j][2], acc[i][j][3]);
        }
    }
    __syncthreads();
    {
        int row   = tid >> 1;
        int cbase = (tid & 1) * 64;
        long gr = blockM + row;
        if (gr < Mrows) {
            int b = (int)(gr / Np);
            int n = (int)(gr - (long)b * Np);
            __half* orow = g_h16 + ((size_t)n * Bp + b) * FOUT + cbase;
            const __half* src = sA + row * SROW + cbase;
            #pragma unroll
            for (int i = 0; i < 8; i++)
                ((uint4*)orow)[i] = *(const uint4*)(src + i * 8);
        }
    }
}

// ---------------------------------------------------------------------------
// SpMM: out[b][r][:] = sum_{e in row r} val[e] * h16[col[e]][b][:]
// Block = 256 threads = 8 warps = 2 rows x 4 batches.
// 8-edge batches (8 gathers in flight -> MLP=8); tail is one masked 8-batch
// (clamped index, zero weight) so short rows never fall into a serial loop.
// ---------------------------------------------------------------------------
__global__ __launch_bounds__(256)
void spmm_kernel(float* __restrict__ out) {
    const int warp = threadIdx.x >> 5;
    const int lane = threadIdx.x & 31;
    const int r = blockIdx.x * 2 + (warp >> 2);
    const int b = warp & 3;
    if (r >= Np) return;

    const int2*  __restrict__ cv = g_colval;
    const __half* __restrict__ h = g_h16;

    const int s = g_offsets[r];
    const int e = g_offsets[r + 1];

    float4 accA = make_float4(0.f, 0.f, 0.f, 0.f);
    float4 accB = make_float4(0.f, 0.f, 0.f, 0.f);

    int i = s;
    for (; i < e; i += 8) {
        // gather 8 edges; clamp out-of-range to s with zero weight
        int2  ce[8];
        uint2 q[8];
        float v[8];
        #pragma unroll
        for (int k = 0; k < 8; k++) {
            int idx = i + k;
            bool ok = idx < e;
            ce[k] = __ldg(&cv[ok ? idx : s]);
            v[k]  = ok ? __int_as_float(ce[k].y) : 0.f;
        }
        #pragma unroll
        for (int k = 0; k < 8; k++)
            q[k] = __ldg((const uint2*)(h + (((size_t)ce[k].x * Bp + b) << 7)) + lane);
        #pragma unroll
        for (int k = 0; k < 8; k += 2) {
            float2 f;
            f = __half22float2(*(__half2*)&q[k].x);
            accA.x += v[k] * f.x; accA.y += v[k] * f.y;
            f = __half22float2(*(__half2*)&q[k].y);
            accA.z += v[k] * f.x; accA.w += v[k] * f.y;
            f = __half22float2(*(__half2*)&q[k + 1].x);
            accB.x += v[k + 1] * f.x; accB.y += v[k + 1] * f.y;
            f = __half22float2(*(__half2*)&q[k + 1].y);
            accB.z += v[k + 1] * f.x; accB.w += v[k + 1] * f.y;
        }
    }

    float4 acc = make_float4(accA.x + accB.x, accA.y + accB.y,
                             accA.z + accB.z, accA.w + accB.w);
    float4* orow = (float4*)(out + ((size_t)b * Np + r) * FOUT);
    orow[lane] = acc;
}

// ---------------------------------------------------------------------------
// Launch — fork CSR build onto a side stream (neutral but free).
// ---------------------------------------------------------------------------
extern "C" void kernel_launch(void* const* d_in, const int* in_sizes, int n_in,
                              void* d_out, int out_size) {
    const float* x  = (const float*)d_in[0];
    const float* W  = (const float*)d_in[1];
    const int*   er = (const int*)d_in[2];
    const int*   ec = (const int*)d_in[3];
    const float* ev = (const float*)d_in[4];
    float* out = (float*)d_out;

    static cudaStream_t s2 = nullptr;
    static cudaEvent_t  evFork = nullptr, evJoin = nullptr;
    static int* counts_ptr = nullptr;
    if (!s2) {
        cudaStreamCreateWithFlags(&s2, cudaStreamNonBlocking);
        cudaEventCreateWithFlags(&evFork, cudaEventDisableTiming);
        cudaEventCreateWithFlags(&evJoin, cudaEventDisableTiming);
        cudaGetSymbolAddress((void**)&counts_ptr, g_counts);
    }

    cudaEventRecord(evFork, 0);
    cudaStreamWaitEvent(s2, evFork, 0);

    // Branch A (legacy stream): dense projection h = x @ W^T
    const int smem_bytes = 2 * 128 * SROW * sizeof(__half);   // 69632
    cudaFuncSetAttribute(gemm_mma_kernel,
                         cudaFuncAttributeMaxDynamicSharedMemorySize, smem_bytes);
    gemm_mma_kernel<<<(Mrows + 127) / 128, 256, smem_bytes>>>(x, W);

    // Branch B (side stream): CSR build
    cudaMemsetAsync(counts_ptr, 0, (Np + 1) * sizeof(int), s2);
    detect_kernel<<<1, 256, 0, s2>>>(er);
    hist_kernel<<<(Ep / 4 + 255) / 256, 256, 0, s2>>>(er);
    const int nScanBlocks = (Np + 1023) / 1024;   // 49
    scan1_kernel<<<nScanBlocks, 1024, 0, s2>>>();
    scan2_kernel<<<1, 64, 0, s2>>>(nScanBlocks);
    scan3_kernel<<<nScanBlocks, 1024, 0, s2>>>();
    scatter_kernel<<<(Ep + 255) / 256, 256, 0, s2>>>(er, ec, ev);

    cudaEventRecord(evJoin, s2);
    cudaStreamWaitEvent(0, evJoin, 0);

    spmm_kernel<<<(Np + 1) / 2, 256>>>(out);
}

// round 8
// speedup vs baseline: 1.2039x; 1.2039x over previous
#include <cuda_runtime.h>
#include <cuda_fp16.h>
#include <stdint.h>

// Problem constants
#define Bp    4
#define Np    50000
#define Ep    800000
#define FIN   128
#define FOUT  128
#define Mrows (Bp * Np)

#define SROW  136   // halfs per smem row (128 + 8 pad -> conflict-free ldmatrix)

// ---------------------------------------------------------------------------
// Device-global scratch (no cudaMalloc allowed)
// ---------------------------------------------------------------------------
__device__ __half g_h16[(size_t)Np * Bp * FOUT];  // 51.2 MB, layout [N][B][F]
__device__ int   g_counts[Np + 1];
__device__ int   g_offsets[Np + 1];
__device__ int   g_rank[Ep];                      // per-edge rank within its row
__device__ int   g_bsum[64];
__device__ int2  g_colval[Ep];                    // packed {col, val_bits}
__device__ int   g_idx64;

// ---------------------------------------------------------------------------
// Detect int32 vs int64 edge indices.
// ---------------------------------------------------------------------------
__global__ void detect_kernel(const int* __restrict__ er) {
    __shared__ int nz;
    if (threadIdx.x == 0) nz = 0;
    __syncthreads();
    for (int j = threadIdx.x; j < 2048; j += blockDim.x)
        if (er[2 * j + 1] != 0) nz = 1;
    __syncthreads();
    if (threadIdx.x == 0) g_idx64 = nz ? 0 : 1;
}

// ---------------------------------------------------------------------------
// Histogram of edge_row + per-edge rank (atomic return value), 4 edges/thread
// ---------------------------------------------------------------------------
__global__ void hist_kernel(const int* __restrict__ er) {
    const int idx64 = g_idx64;
    int base = (blockIdx.x * blockDim.x + threadIdx.x) * 4;
    if (base >= Ep) return;
    int r0, r1, r2, r3;
    if (base + 4 <= Ep) {
        if (idx64) {
            int4 a = __ldg((const int4*)(er + 2 * base));
            int4 b = __ldg((const int4*)(er + 2 * base + 4));
            r0 = a.x; r1 = a.z; r2 = b.x; r3 = b.z;
        } else {
            int4 a = __ldg((const int4*)(er + base));
            r0 = a.x; r1 = a.y; r2 = a.z; r3 = a.w;
        }
        int k0 = atomicAdd(&g_counts[r0], 1);
        int k1 = atomicAdd(&g_counts[r1], 1);
        int k2 = atomicAdd(&g_counts[r2], 1);
        int k3 = atomicAdd(&g_counts[r3], 1);
        *(int4*)(g_rank + base) = make_int4(k0, k1, k2, k3);
    } else {
        for (int j = base; j < Ep; j++) {
            int r = idx64 ? er[2 * j] : er[j];
            g_rank[j] = atomicAdd(&g_counts[r], 1);
        }
    }
}

// ---------------------------------------------------------------------------
// Two-level scan
// ---------------------------------------------------------------------------
__global__ __launch_bounds__(1024)
void scan1_kernel() {
    __shared__ int warpsum[32];
    const int t    = threadIdx.x;
    const int lane = t & 31;
    const int w    = t >> 5;
    int i = blockIdx.x * 1024 + t;
    int v = (i < Np) ? g_counts[i] : 0;

    int x = v;
    #pragma unroll
    for (int off = 1; off < 32; off <<= 1) {
        int y = __shfl_up_sync(0xFFFFFFFFu, x, off);
        if (lane >= off) x += y;
    }
    if (lane == 31) warpsum[w] = x;
    __syncthreads();
    if (w == 0) {
        int s = warpsum[lane];
        #pragma unroll
        for (int off = 1; off < 32; off <<= 1) {
            int y = __shfl_up_sync(0xFFFFFFFFu, s, off);
            if (lane >= off) s += y;
        }
        warpsum[lane] = s;
    }
    __syncthreads();
    int incl = x + (w > 0 ? warpsum[w - 1] : 0);
    if (i < Np) g_offsets[i] = incl;
    if (t == 1023) g_bsum[blockIdx.x] = incl;
}

__global__ void scan2_kernel(int nblocks) {
    __shared__ int sh[64];
    const int t    = threadIdx.x;
    const int lane = t & 31;
    const int w    = t >> 5;
    int v = (t < nblocks) ? g_bsum[t] : 0;
    int x = v;
    #pragma unroll
    for (int off = 1; off < 32; off <<= 1) {
        int y = __shfl_up_sync(0xFFFFFFFFu, x, off);
        if (lane >= off) x += y;
    }
    sh[t] = x;
    __syncthreads();
    int incl = x + (w == 1 ? sh[31] : 0);
    g_bsum[t] = incl - v;
    if (t == nblocks - 1) g_offsets[Np] = incl;
}

__global__ __launch_bounds__(1024)
void scan3_kernel() {
    int i = blockIdx.x * 1024 + threadIdx.x;
    if (i >= Np) return;
    g_offsets[i] = g_bsum[blockIdx.x] + g_offsets[i] - g_counts[i];
}

// ---------------------------------------------------------------------------
// Scatter edges into CSR order — no atomics, 4 edges/thread vectorized
// ---------------------------------------------------------------------------
__global__ void scatter_kernel(const int* __restrict__ er,
                               const int* __restrict__ ec,
                               const float* __restrict__ ev) {
    const int idx64 = g_idx64;
    int base = (blockIdx.x * blockDim.x + threadIdx.x) * 4;
    if (base >= Ep) return;
    if (base + 4 <= Ep) {
        int r0, r1, r2, r3, c0, c1, c2, c3;
        if (idx64) {
            int4 a = __ldg((const int4*)(er + 2 * base));
            int4 b = __ldg((const int4*)(er + 2 * base + 4));
            r0 = a.x; r1 = a.z; r2 = b.x; r3 = b.z;
            int4 ca = __ldg((const int4*)(ec + 2 * base));
            int4 cb = __ldg((const int4*)(ec + 2 * base + 4));
            c0 = ca.x; c1 = ca.z; c2 = cb.x; c3 = cb.z;
        } else {
            int4 a = __ldg((const int4*)(er + base));
            r0 = a.x; r1 = a.y; r2 = a.z; r3 = a.w;
            int4 ca = __ldg((const int4*)(ec + base));
            c0 = ca.x; c1 = ca.y; c2 = ca.z; c3 = ca.w;
        }
        int4   k = __ldg((const int4*)(g_rank + base));
        float4 v = __ldg((const float4*)(ev + base));
        g_colval[g_offsets[r0] + k.x] = make_int2(c0, __float_as_int(v.x));
        g_colval[g_offsets[r1] + k.y] = make_int2(c1, __float_as_int(v.y));
        g_colval[g_offsets[r2] + k.z] = make_int2(c2, __float_as_int(v.z));
        g_colval[g_offsets[r3] + k.w] = make_int2(c3, __float_as_int(v.w));
    } else {
        for (int j = base; j < Ep; j++) {
            int r = idx64 ? er[2 * j] : er[j];
            int c = idx64 ? ec[2 * j] : ec[j];
            g_colval[g_offsets[r] + g_rank[j]] = make_int2(c, __float_as_int(ev[j]));
        }
    }
}

// ---------------------------------------------------------------------------
// Tensor-core GEMM: h = x @ W^T, fp16 in (converted on load), fp32 acc.
// CTA: 128x128, K=128 single pass. 8 warps, warp tile 32x64, m16n8k16.
// ---------------------------------------------------------------------------
__global__ __launch_bounds__(256, 2)
void gemm_mma_kernel(const float* __restrict__ A, const float* __restrict__ W) {
    extern __shared__ __half smem[];
    __half* sA = smem;                  // 128 x SROW
    __half* sB = smem + 128 * SROW;     // 128 x SROW

    const int tid  = threadIdx.x;
    const int lane = tid & 31;
    const int wid  = tid >> 5;
    const long blockM = (long)blockIdx.x * 128;

    {
        int row   = tid >> 1;
        int cbase = (tid & 1) * 64;
        long gr = blockM + row;
        bool valid = gr < Mrows;
        const float4* src = (const float4*)(A + gr * 128 + cbase);
        __half* dst = sA + row * SROW + cbase;
        #pragma unroll
        for (int i = 0; i < 16; i++) {
            float4 v = valid ? __ldg(src + i) : make_float4(0.f, 0.f, 0.f, 0.f);
            *(__half2*)(dst + i * 4)     = __floats2half2_rn(v.x, v.y);
            *(__half2*)(dst + i * 4 + 2) = __floats2half2_rn(v.z, v.w);
        }
        const float4* wsrc = (const float4*)(W + row * 128 + cbase);
        __half* wdst = sB + row * SROW + cbase;
        #pragma unroll
        for (int i = 0; i < 16; i++) {
            float4 v = __ldg(wsrc + i);
            *(__half2*)(wdst + i * 4)     = __floats2half2_rn(v.x, v.y);
            *(__half2*)(wdst + i * 4 + 2) = __floats2half2_rn(v.z, v.w);
        }
    }
    __syncthreads();

    const int wm = wid & 3;
    const int wn = wid >> 2;
    const int a_row = wm * 32;
    const int b_n   = wn * 64;

    float acc[2][8][4];
    #pragma unroll
    for (int i = 0; i < 2; i++)
        #pragma unroll
        for (int j = 0; j < 8; j++)
            #pragma unroll
            for (int q = 0; q < 4; q++) acc[i][j][q] = 0.f;

    uint32_t sA_base = (uint32_t)__cvta_generic_to_shared(sA);
    uint32_t sB_base = (uint32_t)__cvta_generic_to_shared(sB);

    #pragma unroll
    for (int kk = 0; kk < 8; kk++) {
        uint32_t a[2][4];
        #pragma unroll
        for (int i = 0; i < 2; i++) {
            uint32_t addr = sA_base +
                (((a_row + i * 16 + (lane & 15)) * SROW + kk * 16 + (lane >> 4) * 8) << 1);
            asm volatile(
                "ldmatrix.sync.aligned.m8n8.x4.shared.b16 {%0,%1,%2,%3}, [%4];"
                : "=r"(a[i][0]), "=r"(a[i][1]), "=r"(a[i][2]), "=r"(a[i][3])
                : "r"(addr));
        }
        uint32_t b[8][2];
        #pragma unroll
        for (int j = 0; j < 8; j++) {
            int ln   = lane & 7;
            int koff = (lane & 8) ? 8 : 0;
            uint32_t addr = sB_base +
                (((b_n + j * 8 + ln) * SROW + kk * 16 + koff) << 1);
            asm volatile(
                "ldmatrix.sync.aligned.m8n8.x2.shared.b16 {%0,%1}, [%2];"
                : "=r"(b[j][0]), "=r"(b[j][1]) : "r"(addr));
        }
        #pragma unroll
        for (int i = 0; i < 2; i++)
            #pragma unroll
            for (int j = 0; j < 8; j++)
                asm volatile(
                    "mma.sync.aligned.m16n8k16.row.col.f32.f16.f16.f32 "
                    "{%0,%1,%2,%3}, {%4,%5,%6,%7}, {%8,%9}, {%0,%1,%2,%3};"
                    : "+f"(acc[i][j][0]), "+f"(acc[i][j][1]),
                      "+f"(acc[i][j][2]), "+f"(acc[i][j][3])
                    : "r"(a[i][0]), "r"(a[i][1]), "r"(a[i][2]), "r"(a[i][3]),
                      "r"(b[j][0]), "r"(b[j][1]));
    }

    __syncthreads();
    #pragma unroll
    for (int i = 0; i < 2; i++) {
        int row0 = a_row + i * 16 + (lane >> 2);
        #pragma unroll
        for (int j = 0; j < 8; j++) {
            int col = b_n + j * 8 + (lane & 3) * 2;
            *(__half2*)(sA + row0 * SROW + col) =
                __floats2half2_rn(acc[i][j][0], acc[i][j][1]);
            *(__half2*)(sA + (row0 + 8) * SROW + col) =
                __floats2half2_rn(acc[i][j][2], acc[i][j][3]);
        }
    }
    __syncthreads();
    {
        int row   = tid >> 1;
        int cbase = (tid & 1) * 64;
        long gr = blockM + row;
        if (gr < Mrows) {
            int b = (int)(gr / Np);
            int n = (int)(gr - (long)b * Np);
            __half* orow = g_h16 + ((size_t)n * Bp + b) * FOUT + cbase;
            const __half* src = sA + row * SROW + cbase;
            #pragma unroll
            for (int i = 0; i < 8; i++)
                ((uint4*)orow)[i] = *(const uint4*)(src + i * 8);
        }
    }
}

// ---------------------------------------------------------------------------
// SpMM: one warp = one row, ALL 4 batches.
// Per edge the warp reads the full 1KB node block h16[c][0..3][0..127] as
// two LDG.128 per lane (lane covers 16B; +512B covers batches 2/3).
// Lane l accumulates 8 floats for batch (l>>4) and 8 for batch 2+(l>>4),
// features ((l*8)&127)..+8.  2-edge unroll, masked pair tail.
// ---------------------------------------------------------------------------
__global__ __launch_bounds__(256)
void spmm_kernel(float* __restrict__ out) {
    const int warp = threadIdx.x >> 5;
    const int lane = threadIdx.x & 31;
    const int r = blockIdx.x * 8 + warp;
    if (r >= Np) return;

    const int2*  __restrict__ cv = g_colval;
    const __half* __restrict__ h = g_h16;

    const int s = g_offsets[r];
    const int e = g_offsets[r + 1];

    float acc0[8], acc1[8];
    #pragma unroll
    for (int j = 0; j < 8; j++) { acc0[j] = 0.f; acc1[j] = 0.f; }

    const int loff = lane * 8;  // half offset within 256-half group

    for (int i = s; i < e; i += 2) {
        int2 e0 = __ldg(&cv[i]);
        bool ok1 = (i + 1) < e;
        int2 e1 = __ldg(&cv[ok1 ? i + 1 : i]);
        float v0 = __int_as_float(e0.y);
        float v1 = ok1 ? __int_as_float(e1.y) : 0.f;

        const __half* p0 = h + ((size_t)e0.x << 9);   // 512 halfs per node
        const __half* p1 = h + ((size_t)e1.x << 9);
        uint4 q0a = __ldg((const uint4*)(p0 + loff));
        uint4 q0b = __ldg((const uint4*)(p0 + 256 + loff));
        uint4 q1a = __ldg((const uint4*)(p1 + loff));
        uint4 q1b = __ldg((const uint4*)(p1 + 256 + loff));

        const unsigned* w0a = (const unsigned*)&q0a;
        const unsigned* w0b = (const unsigned*)&q0b;
        const unsigned* w1a = (const unsigned*)&q1a;
        const unsigned* w1b = (const unsigned*)&q1b;
        #pragma unroll
        for (int j = 0; j < 4; j++) {
            float2 f;
            f = __half22float2(*(const __half2*)&w0a[j]);
            acc0[2 * j]     += v0 * f.x;
            acc0[2 * j + 1] += v0 * f.y;
            f = __half22float2(*(const __half2*)&w0b[j]);
            acc1[2 * j]     += v0 * f.x;
            acc1[2 * j + 1] += v0 * f.y;
            f = __half22float2(*(const __half2*)&w1a[j]);
            acc0[2 * j]     += v1 * f.x;
            acc0[2 * j + 1] += v1 * f.y;
            f = __half22float2(*(const __half2*)&w1b[j]);
            acc1[2 * j]     += v1 * f.x;
            acc1[2 * j + 1] += v1 * f.y;
        }
    }

    // write-out: batch b0 = lane>>4 (acc0), b1 = 2+(lane>>4) (acc1),
    // features f0 = (lane*8) & 127 .. +8
    const int b0 = lane >> 4;
    const int f0 = loff & 127;
    float* o0 = out + ((size_t)b0 * Np + r) * FOUT + f0;
    float* o1 = out + ((size_t)(b0 + 2) * Np + r) * FOUT + f0;
    *(float4*)(o0)     = make_float4(acc0[0], acc0[1], acc0[2], acc0[3]);
    *(float4*)(o0 + 4) = make_float4(acc0[4], acc0[5], acc0[6], acc0[7]);
    *(float4*)(o1)     = make_float4(acc1[0], acc1[1], acc1[2], acc1[3]);
    *(float4*)(o1 + 4) = make_float4(acc1[4], acc1[5], acc1[6], acc1[7]);
}

// ---------------------------------------------------------------------------
// Launch — fork CSR build onto a side stream.
// ---------------------------------------------------------------------------
extern "C" void kernel_launch(void* const* d_in, const int* in_sizes, int n_in,
                              void* d_out, int out_size) {
    const float* x  = (const float*)d_in[0];
    const float* W  = (const float*)d_in[1];
    const int*   er = (const int*)d_in[2];
    const int*   ec = (const int*)d_in[3];
    const float* ev = (const float*)d_in[4];
    float* out = (float*)d_out;

    static cudaStream_t s2 = nullptr;
    static cudaEvent_t  evFork = nullptr, evJoin = nullptr;
    static int* counts_ptr = nullptr;
    if (!s2) {
        cudaStreamCreateWithFlags(&s2, cudaStreamNonBlocking);
        cudaEventCreateWithFlags(&evFork, cudaEventDisableTiming);
        cudaEventCreateWithFlags(&evJoin, cudaEventDisableTiming);
        cudaGetSymbolAddress((void**)&counts_ptr, g_counts);
    }

    cudaEventRecord(evFork, 0);
    cudaStreamWaitEvent(s2, evFork, 0);

    // Branch A (legacy stream): dense projection h = x @ W^T
    const int smem_bytes = 2 * 128 * SROW * sizeof(__half);   // 69632
    cudaFuncSetAttribute(gemm_mma_kernel,
                         cudaFuncAttributeMaxDynamicSharedMemorySize, smem_bytes);
    gemm_mma_kernel<<<(Mrows + 127) / 128, 256, smem_bytes>>>(x, W);

    // Branch B (side stream): CSR build
    cudaMemsetAsync(counts_ptr, 0, (Np + 1) * sizeof(int), s2);
    detect_kernel<<<1, 256, 0, s2>>>(er);
    hist_kernel<<<(Ep / 4 + 255) / 256, 256, 0, s2>>>(er);
    const int nScanBlocks = (Np + 1023) / 1024;   // 49
    scan1_kernel<<<nScanBlocks, 1024, 0, s2>>>();
    scan2_kernel<<<1, 64, 0, s2>>>(nScanBlocks);
    scan3_kernel<<<nScanBlocks, 1024, 0, s2>>>();
    scatter_kernel<<<(Ep / 4 + 255) / 256, 256, 0, s2>>>(er, ec, ev);

    cudaEventRecord(evJoin, s2);
    cudaStreamWaitEvent(0, evJoin, 0);

    spmm_kernel<<<(Np + 7) / 8, 256>>>(out);
}

// round 9
// speedup vs baseline: 1.2766x; 1.0604x over previous
#include <cuda_runtime.h>
#include <cuda_fp16.h>
#include <stdint.h>

// Problem constants
#define Bp    4
#define Np    50000
#define Ep    800000
#define FIN   128
#define FOUT  128
#define Mrows (Bp * Np)
#define HalfRows (Mrows / 2)       // 100000 rows per GEMM half (2 batches)

#define SROW  136   // halfs per smem row (128 + 8 pad -> conflict-free ldmatrix)

// ---------------------------------------------------------------------------
// Device-global scratch (no cudaMalloc allowed)
// ---------------------------------------------------------------------------
__device__ __half g_h16[(size_t)Np * Bp * FOUT];  // 51.2 MB, layout [N][B][F]
__device__ int   g_counts[Np + 1];
__device__ int   g_offsets[Np + 1];
__device__ int   g_rank[Ep];
__device__ int   g_bsum[64];
__device__ int2  g_colval[Ep];
__device__ int   g_idx64;

// ---------------------------------------------------------------------------
// Zero histogram + detect int32 vs int64 edge indices (block 0).
// ---------------------------------------------------------------------------
__global__ void zero_detect_kernel(const int* __restrict__ er) {
    int i = blockIdx.x * blockDim.x + threadIdx.x;
    if (i <= Np) g_counts[i] = 0;
    if (blockIdx.x == 0) {
        __shared__ int nz;
        if (threadIdx.x == 0) nz = 0;
        __syncthreads();
        for (int j = threadIdx.x; j < 2048; j += blockDim.x)
            if (er[2 * j + 1] != 0) nz = 1;
        __syncthreads();
        if (threadIdx.x == 0) g_idx64 = nz ? 0 : 1;
    }
}

// ---------------------------------------------------------------------------
// Histogram of edge_row + per-edge rank, 4 edges/thread
// ---------------------------------------------------------------------------
__global__ void hist_kernel(const int* __restrict__ er) {
    const int idx64 = g_idx64;
    int base = (blockIdx.x * blockDim.x + threadIdx.x) * 4;
    if (base >= Ep) return;
    int r0, r1, r2, r3;
    if (base + 4 <= Ep) {
        if (idx64) {
            int4 a = __ldg((const int4*)(er + 2 * base));
            int4 b = __ldg((const int4*)(er + 2 * base + 4));
            r0 = a.x; r1 = a.z; r2 = b.x; r3 = b.z;
        } else {
            int4 a = __ldg((const int4*)(er + base));
            r0 = a.x; r1 = a.y; r2 = a.z; r3 = a.w;
        }
        int k0 = atomicAdd(&g_counts[r0], 1);
        int k1 = atomicAdd(&g_counts[r1], 1);
        int k2 = atomicAdd(&g_counts[r2], 1);
        int k3 = atomicAdd(&g_counts[r3], 1);
        *(int4*)(g_rank + base) = make_int4(k0, k1, k2, k3);
    } else {
        for (int j = base; j < Ep; j++) {
            int r = idx64 ? er[2 * j] : er[j];
            g_rank[j] = atomicAdd(&g_counts[r], 1);
        }
    }
}

// ---------------------------------------------------------------------------
// Two-level scan
// ---------------------------------------------------------------------------
__global__ __launch_bounds__(1024)
void scan1_kernel() {
    __shared__ int warpsum[32];
    const int t    = threadIdx.x;
    const int lane = t & 31;
    const int w    = t >> 5;
    int i = blockIdx.x * 1024 + t;
    int v = (i < Np) ? g_counts[i] : 0;

    int x = v;
    #pragma unroll
    for (int off = 1; off < 32; off <<= 1) {
        int y = __shfl_up_sync(0xFFFFFFFFu, x, off);
        if (lane >= off) x += y;
    }
    if (lane == 31) warpsum[w] = x;
    __syncthreads();
    if (w == 0) {
        int s = warpsum[lane];
        #pragma unroll
        for (int off = 1; off < 32; off <<= 1) {
            int y = __shfl_up_sync(0xFFFFFFFFu, s, off);
            if (lane >= off) s += y;
        }
        warpsum[lane] = s;
    }
    __syncthreads();
    int incl = x + (w > 0 ? warpsum[w - 1] : 0);
    if (i < Np) g_offsets[i] = incl;
    if (t == 1023) g_bsum[blockIdx.x] = incl;
}

__global__ void scan2_kernel(int nblocks) {
    __shared__ int sh[64];
    const int t    = threadIdx.x;
    const int lane = t & 31;
    const int w    = t >> 5;
    int v = (t < nblocks) ? g_bsum[t] : 0;
    int x = v;
    #pragma unroll
    for (int off = 1; off < 32; off <<= 1) {
        int y = __shfl_up_sync(0xFFFFFFFFu, x, off);
        if (lane >= off) x += y;
    }
    sh[t] = x;
    __syncthreads();
    int incl = x + (w == 1 ? sh[31] : 0);
    g_bsum[t] = incl - v;
    if (t == nblocks - 1) g_offsets[Np] = incl;
}

__global__ __launch_bounds__(1024)
void scan3_kernel() {
    int i = blockIdx.x * 1024 + threadIdx.x;
    if (i >= Np) return;
    g_offsets[i] = g_bsum[blockIdx.x] + g_offsets[i] - g_counts[i];
}

// ---------------------------------------------------------------------------
// Scatter edges into CSR order — no atomics, 4 edges/thread vectorized
// ---------------------------------------------------------------------------
__global__ void scatter_kernel(const int* __restrict__ er,
                               const int* __restrict__ ec,
                               const float* __restrict__ ev) {
    const int idx64 = g_idx64;
    int base = (blockIdx.x * blockDim.x + threadIdx.x) * 4;
    if (base >= Ep) return;
    if (base + 4 <= Ep) {
        int r0, r1, r2, r3, c0, c1, c2, c3;
        if (idx64) {
            int4 a = __ldg((const int4*)(er + 2 * base));
            int4 b = __ldg((const int4*)(er + 2 * base + 4));
            r0 = a.x; r1 = a.z; r2 = b.x; r3 = b.z;
            int4 ca = __ldg((const int4*)(ec + 2 * base));
            int4 cb = __ldg((const int4*)(ec + 2 * base + 4));
            c0 = ca.x; c1 = ca.z; c2 = cb.x; c3 = cb.z;
        } else {
            int4 a = __ldg((const int4*)(er + base));
            r0 = a.x; r1 = a.y; r2 = a.z; r3 = a.w;
            int4 ca = __ldg((const int4*)(ec + base));
            c0 = ca.x; c1 = ca.y; c2 = ca.z; c3 = ca.w;
        }
        int4   k = __ldg((const int4*)(g_rank + base));
        float4 v = __ldg((const float4*)(ev + base));
        g_colval[g_offsets[r0] + k.x] = make_int2(c0, __float_as_int(v.x));
        g_colval[g_offsets[r1] + k.y] = make_int2(c1, __float_as_int(v.y));
        g_colval[g_offsets[r2] + k.z] = make_int2(c2, __float_as_int(v.z));
        g_colval[g_offsets[r3] + k.w] = make_int2(c3, __float_as_int(v.w));
    } else {
        for (int j = base; j < Ep; j++) {
            int r = idx64 ? er[2 * j] : er[j];
            int c = idx64 ? ec[2 * j] : ec[j];
            g_colval[g_offsets[r] + g_rank[j]] = make_int2(c, __float_as_int(ev[j]));
        }
    }
}

// ---------------------------------------------------------------------------
// Tensor-core GEMM over a row range: h = x @ W^T, fp16 in, fp32 acc.
// row0 selects which half (batches {0,1} or {2,3}) this launch computes.
// ---------------------------------------------------------------------------
__global__ __launch_bounds__(256, 2)
void gemm_mma_kernel(const float* __restrict__ A, const float* __restrict__ W,
                     int row0) {
    extern __shared__ __half smem[];
    __half* sA = smem;                  // 128 x SROW
    __half* sB = smem + 128 * SROW;     // 128 x SROW

    const int tid  = threadIdx.x;
    const int lane = tid & 31;
    const int wid  = tid >> 5;
    const long blockM = (long)row0 + (long)blockIdx.x * 128;
    const long rowEnd = (long)row0 + HalfRows;

    {
        int row   = tid >> 1;
        int cbase = (tid & 1) * 64;
        long gr = blockM + row;
        bool valid = gr < rowEnd;
        const float4* src = (const float4*)(A + gr * 128 + cbase);
        __half* dst = sA + row * SROW + cbase;
        #pragma unroll
        for (int i = 0; i < 16; i++) {
            float4 v = valid ? __ldg(src + i) : make_float4(0.f, 0.f, 0.f, 0.f);
            *(__half2*)(dst + i * 4)     = __floats2half2_rn(v.x, v.y);
            *(__half2*)(dst + i * 4 + 2) = __floats2half2_rn(v.z, v.w);
        }
        const float4* wsrc = (const float4*)(W + row * 128 + cbase);
        __half* wdst = sB + row * SROW + cbase;
        #pragma unroll
        for (int i = 0; i < 16; i++) {
            float4 v = __ldg(wsrc + i);
            *(__half2*)(wdst + i * 4)     = __floats2half2_rn(v.x, v.y);
            *(__half2*)(wdst + i * 4 + 2) = __floats2half2_rn(v.z, v.w);
        }
    }
    __syncthreads();

    const int wm = wid & 3;
    const int wn = wid >> 2;
    const int a_row = wm * 32;
    const int b_n   = wn * 64;

    float acc[2][8][4];
    #pragma unroll
    for (int i = 0; i < 2; i++)
        #pragma unroll
        for (int j = 0; j < 8; j++)
            #pragma unroll
            for (int q = 0; q < 4; q++) acc[i][j][q] = 0.f;

    uint32_t sA_base = (uint32_t)__cvta_generic_to_shared(sA);
    uint32_t sB_base = (uint32_t)__cvta_generic_to_shared(sB);

    #pragma unroll
    for (int kk = 0; kk < 8; kk++) {
        uint32_t a[2][4];
        #pragma unroll
        for (int i = 0; i < 2; i++) {
            uint32_t addr = sA_base +
                (((a_row + i * 16 + (lane & 15)) * SROW + kk * 16 + (lane >> 4) * 8) << 1);
            asm volatile(
                "ldmatrix.sync.aligned.m8n8.x4.shared.b16 {%0,%1,%2,%3}, [%4];"
                : "=r"(a[i][0]), "=r"(a[i][1]), "=r"(a[i][2]), "=r"(a[i][3])
                : "r"(addr));
        }
        uint32_t b[8][2];
        #pragma unroll
        for (int j = 0; j < 8; j++) {
            int ln   = lane & 7;
            int koff = (lane & 8) ? 8 : 0;
            uint32_t addr = sB_base +
                (((b_n + j * 8 + ln) * SROW + kk * 16 + koff) << 1);
            asm volatile(
                "ldmatrix.sync.aligned.m8n8.x2.shared.b16 {%0,%1}, [%2];"
                : "=r"(b[j][0]), "=r"(b[j][1]) : "r"(addr));
        }
        #pragma unroll
        for (int i = 0; i < 2; i++)
            #pragma unroll
            for (int j = 0; j < 8; j++)
                asm volatile(
                    "mma.sync.aligned.m16n8k16.row.col.f32.f16.f16.f32 "
                    "{%0,%1,%2,%3}, {%4,%5,%6,%7}, {%8,%9}, {%0,%1,%2,%3};"
                    : "+f"(acc[i][j][0]), "+f"(acc[i][j][1]),
                      "+f"(acc[i][j][2]), "+f"(acc[i][j][3])
                    : "r"(a[i][0]), "r"(a[i][1]), "r"(a[i][2]), "r"(a[i][3]),
                      "r"(b[j][0]), "r"(b[j][1]));
    }

    __syncthreads();
    #pragma unroll
    for (int i = 0; i < 2; i++) {
        int row0w = a_row + i * 16 + (lane >> 2);
        #pragma unroll
        for (int j = 0; j < 8; j++) {
            int col = b_n + j * 8 + (lane & 3) * 2;
            *(__half2*)(sA + row0w * SROW + col) =
                __floats2half2_rn(acc[i][j][0], acc[i][j][1]);
            *(__half2*)(sA + (row0w + 8) * SROW + col) =
                __floats2half2_rn(acc[i][j][2], acc[i][j][3]);
        }
    }
    __syncthreads();
    {
        int row   = tid >> 1;
        int cbase = (tid & 1) * 64;
        long gr = blockM + row;
        if (gr < rowEnd) {
            int b = (int)(gr / Np);
            int n = (int)(gr - (long)b * Np);
            __half* orow = g_h16 + ((size_t)n * Bp + b) * FOUT + cbase;
            const __half* src = sA + row * SROW + cbase;
            #pragma unroll
            for (int i = 0; i < 8; i++)
                ((uint4*)orow)[i] = *(const uint4*)(src + i * 8);
        }
    }
}

// ---------------------------------------------------------------------------
// SpMM half: one warp = one row, batches {b_base, b_base+1}.
// Per edge the warp reads 512B (h16[c][b_base..b_base+1][:]) as one LDG.128
// per lane. Lane l: batch b_base+(l>>4), features ((l*8)&127)..+8.
// 2-edge unroll, masked second edge.
// ---------------------------------------------------------------------------
__global__ __launch_bounds__(256)
void spmm_half_kernel(float* __restrict__ out, int b_base) {
    const int warp = threadIdx.x >> 5;
    const int lane = threadIdx.x & 31;
    const int r = blockIdx.x * 8 + warp;
    if (r >= Np) return;

    const int2*  __restrict__ cv = g_colval;
    const __half* __restrict__ h = g_h16 + b_base * FOUT;  // +0 or +256 halfs

    const int s = g_offsets[r];
    const int e = g_offsets[r + 1];

    float acc[8];
    #pragma unroll
    for (int j = 0; j < 8; j++) acc[j] = 0.f;

    const int loff = lane * 8;  // half offset within the 256-half pair-block

    for (int i = s; i < e; i += 2) {
        int2 e0 = __ldg(&cv[i]);
        bool ok1 = (i + 1) < e;
        int2 e1 = __ldg(&cv[ok1 ? i + 1 : i]);
        float v0 = __int_as_float(e0.y);
        float v1 = ok1 ? __int_as_float(e1.y) : 0.f;

        const __half* p0 = h + ((size_t)e0.x << 9);
        const __half* p1 = h + ((size_t)e1.x << 9);
        uint4 q0 = __ldg((const uint4*)(p0 + loff));
        uint4 q1 = __ldg((const uint4*)(p1 + loff));

        const unsigned* w0 = (const unsigned*)&q0;
        const unsigned* w1 = (const unsigned*)&q1;
        #pragma unroll
        for (int j = 0; j < 4; j++) {
            float2 f;
            f = __half22float2(*(const __half2*)&w0[j]);
            acc[2 * j]     += v0 * f.x;
            acc[2 * j + 1] += v0 * f.y;
            f = __half22float2(*(const __half2*)&w1[j]);
            acc[2 * j]     += v1 * f.x;
            acc[2 * j + 1] += v1 * f.y;
        }
    }

    const int b  = b_base + (lane >> 4);
    const int f0 = loff & 127;
    float* o = out + ((size_t)b * Np + r) * FOUT + f0;
    *(float4*)(o)     = make_float4(acc[0], acc[1], acc[2], acc[3]);
    *(float4*)(o + 4) = make_float4(acc[4], acc[5], acc[6], acc[7]);
}

// ---------------------------------------------------------------------------
// Launch — three-way pipeline:
//   legacy: GEMM01 -> GEMM23 -> (wait CSR) SpMM23 -> (join SpMM01)
//   s2:     CSR chain
//   s3:     (wait GEMM01, CSR) SpMM01   — overlaps GEMM23
// ---------------------------------------------------------------------------
extern "C" void kernel_launch(void* const* d_in, const int* in_sizes, int n_in,
                              void* d_out, int out_size) {
    const float* x  = (const float*)d_in[0];
    const float* W  = (const float*)d_in[1];
    const int*   er = (const int*)d_in[2];
    const int*   ec = (const int*)d_in[3];
    const float* ev = (const float*)d_in[4];
    float* out = (float*)d_out;

    static cudaStream_t s2 = nullptr, s3 = nullptr;
    static cudaEvent_t evFork = nullptr, evCSR = nullptr, evG0 = nullptr, evS0 = nullptr;
    if (!s2) {
        cudaStreamCreateWithFlags(&s2, cudaStreamNonBlocking);
        cudaStreamCreateWithFlags(&s3, cudaStreamNonBlocking);
        cudaEventCreateWithFlags(&evFork, cudaEventDisableTiming);
        cudaEventCreateWithFlags(&evCSR, cudaEventDisableTiming);
        cudaEventCreateWithFlags(&evG0, cudaEventDisableTiming);
        cudaEventCreateWithFlags(&evS0, cudaEventDisableTiming);
    }

    const int smem_bytes = 2 * 128 * SROW * sizeof(__half);   // 69632
    cudaFuncSetAttribute(gemm_mma_kernel,
                         cudaFuncAttributeMaxDynamicSharedMemorySize, smem_bytes);

    const int gemmBlocks = (HalfRows + 127) / 128;   // 782
    const int spmmBlocks = (Np + 7) / 8;

    // Fork CSR branch
    cudaEventRecord(evFork, 0);
    cudaStreamWaitEvent(s2, evFork, 0);

    // Legacy: GEMM batches {0,1}, then {2,3}
    gemm_mma_kernel<<<gemmBlocks, 256, smem_bytes>>>(x, W, 0);
    cudaEventRecord(evG0, 0);
    gemm_mma_kernel<<<gemmBlocks, 256, smem_bytes>>>(x, W, HalfRows);

    // s2: CSR build
    zero_detect_kernel<<<(Np + 256) / 256, 256, 0, s2>>>(er);
    hist_kernel<<<(Ep / 4 + 255) / 256, 256, 0, s2>>>(er);
    const int nScanBlocks = (Np + 1023) / 1024;   // 49
    scan1_kernel<<<nScanBlocks, 1024, 0, s2>>>();
    scan2_kernel<<<1, 64, 0, s2>>>(nScanBlocks);
    scan3_kernel<<<nScanBlocks, 1024, 0, s2>>>();
    scatter_kernel<<<(Ep / 4 + 255) / 256, 256, 0, s2>>>(er, ec, ev);
    cudaEventRecord(evCSR, s2);

    // s3: SpMM batches {0,1} — runs concurrently with GEMM {2,3}
    cudaStreamWaitEvent(s3, evG0, 0);
    cudaStreamWaitEvent(s3, evCSR, 0);
    spmm_half_kernel<<<spmmBlocks, 256, 0, s3>>>(out, 0);
    cudaEventRecord(evS0, s3);

    // Legacy: SpMM batches {2,3}, then join SpMM {0,1}
    cudaStreamWaitEvent(0, evCSR, 0);
    spmm_half_kernel<<<spmmBlocks, 256, 0>>>(out, 2);
    cudaStreamWaitEvent(0, evS0, 0);
}